// round 11
// baseline (speedup 1.0000x reference)
#include <cuda_runtime.h>
#include <cstdint>
#include <math.h>

#define BB   64
#define NN   64
#define DD   256
#define LAPD 16
#define MM   2016          // N*(N-1)/2
#define SEQ  2081          // 1 + N + M

__device__ float g_proju[BB * NN * DD];   // 4 MB (C folded in)
__device__ float g_projv[BB * NN * DD];   // 4 MB
__device__ unsigned short g_edge[BB * MM];
__device__ int g_count[BB];

// Map linear upper-tri index m -> (i, j), i<j, row-major (triu_indices order)
__device__ __forceinline__ void m2ij(int m, int& i, int& j) {
    int ii = (int)((127.0 - sqrt(16129.0 - 8.0 * (double)m)) * 0.5);
    if (ii < 0) ii = 0;
    if (ii > 62) ii = 62;
    while (ii < 62 && (ii + 1) * (127 - (ii + 1)) / 2 <= m) ii++;
    while (ii > 0 && ii * (127 - ii) / 2 > m) ii--;
    i = ii;
    j = ii + 1 + (m - ii * (127 - ii) / 2);
}

// Fused: blocks [0,256) = proj; blocks [256,320) = scan + edge mask tail.
__global__ void fused_proj_scan(const float* __restrict__ node_feats,
                                const float* __restrict__ eigvec,
                                const float* __restrict__ W_lap,
                                const float* __restrict__ W_edge,
                                const float* __restrict__ b_edge,
                                const float* __restrict__ type_embed,
                                const float* __restrict__ graph_tok,
                                const int*  __restrict__ adj,
                                float* __restrict__ out) {
    __shared__ float sh[256];
    int tid = threadIdx.x;

    if (blockIdx.x < 256) {
        // ---------------- proj ----------------
        int b  = blockIdx.x >> 2;
        int g  = blockIdx.x & 3;
        int n0 = g * 16;
        int d  = tid;

        float wl[LAPD], wu[LAPD], wv[LAPD];
#pragma unroll
        for (int l = 0; l < LAPD; l++) {
            wl[l] = __ldg(&W_lap[l * DD + d]);
            wu[l] = __ldg(&W_edge[(1 + l) * DD + d]);
            wv[l] = __ldg(&W_edge[(1 + LAPD + l) * DD + d]);
        }
        float Cd = __ldg(&W_edge[d]) + __ldg(&b_edge[d]) + __ldg(&type_embed[DD + d]);

        sh[tid] = eigvec[(size_t)(b * NN + n0) * LAPD + tid];
        __syncthreads();

#pragma unroll 4
        for (int n = 0; n < 16; n++) {
            int node = b * NN + n0 + n;
            float nt = node_feats[(size_t)node * DD + d];
            float pu = 0.f, pv = 0.f;
#pragma unroll
            for (int l = 0; l < LAPD; l++) {
                float ev = sh[n * LAPD + l];
                nt += ev * wl[l];
                pu += ev * wu[l];
                pv += ev * wv[l];
            }
            __stcs(&out[((size_t)b * SEQ + 1 + n0 + n) * DD + d], nt);
            g_proju[(size_t)node * DD + d] = pu + Cd;
            g_projv[(size_t)node * DD + d] = pv;
        }

        if (g == 0) {
            __stcs(&out[(size_t)b * SEQ * DD + d], graph_tok[d]);
            float* maskf = out + (size_t)BB * SEQ * DD;
            if (d < 1 + NN) maskf[(size_t)b * SEQ + d] = 0.f;
        }
    } else {
        // ---------------- scan (shuffle-based) + mask tail ----------------
        int b = blockIdx.x - 256;
        const int* adjb = adj + (size_t)b * NN * NN;
        int lane = tid & 31;
        int wid  = tid >> 5;

        int m0 = tid * 8;
        int i, j;
        int v[8], ij[8];
        int local = 0;
        if (m0 < MM) {
            m2ij(m0, i, j);
#pragma unroll
            for (int q = 0; q < 8; q++) {
                int m = m0 + q;
                int val = 0, pack = 0;
                if (m < MM) {
                    pack = (i << 6) | j;
                    val = adjb[i * NN + j] > 0;
                    j++;
                    if (j == NN) { i++; j = i + 1; }
                }
                v[q] = val; ij[q] = pack;
                local += val;
            }
        } else {
#pragma unroll
            for (int q = 0; q < 8; q++) { v[q] = 0; ij[q] = 0; }
        }

        // warp-inclusive scan of local
        int inc = local;
#pragma unroll
        for (int off = 1; off < 32; off <<= 1) {
            int n = __shfl_up_sync(0xFFFFFFFFu, inc, off);
            if (lane >= off) inc += n;
        }
        int* wsum = (int*)sh;
        if (lane == 31) wsum[wid] = inc;
        __syncthreads();
        int woff = 0;
        if (wid > 0) {
#pragma unroll
            for (int w = 0; w < 7; w++)
                if (w < wid) woff += wsum[w];
        }
        int pos = woff + inc - local;   // exclusive prefix
#pragma unroll
        for (int q = 0; q < 8; q++) {
            if (v[q]) g_edge[b * MM + pos++] = (unsigned short)ij[q];
        }
        __syncthreads();
        int total = wsum[0] + wsum[1] + wsum[2] + wsum[3]
                  + wsum[4] + wsum[5] + wsum[6] + wsum[7];
        if (tid == 0) g_count[b] = total;

        float* maskf = out + (size_t)BB * SEQ * DD + (size_t)b * SEQ + 1 + NN;
        for (int k = tid; k < MM; k += 256)
            maskf[k] = (k < total) ? 0.f : 1.f;
    }
}

// Edge kernel: grid (126, 64), 256 threads. 16 rows/block; each 64-lane group
// handles 4 ADJACENT rows (one u64 load = 4 u16 indices; 8 gather LDG.128 in
// flight). Padding groups take an early store-only zero path. Boundary group
// clamps invalid indices to row 0 (single hot line).
__global__ void __launch_bounds__(256) edge_kernel(float* __restrict__ out) {
    int b    = blockIdx.y;
    int tid  = threadIdx.x;
    int rg   = tid >> 6;                   // 0..3
    int lane = tid & 63;
    int k0   = (blockIdx.x << 4) + (rg << 2);   // rows k0..k0+3
    int K    = g_count[b];

    float4* orow = (float4*)(out + ((size_t)b * SEQ + 1 + NN + k0) * DD);
    float4 z = make_float4(0.f, 0.f, 0.f, 0.f);

    if (k0 >= K) {
        __stcs(&orow[lane],       z);
        __stcs(&orow[64 + lane],  z);
        __stcs(&orow[128 + lane], z);
        __stcs(&orow[192 + lane], z);
        return;
    }

    unsigned long long pk = *(const unsigned long long*)(g_edge + b * MM + k0);
    bool v1 = (k0 + 1 < K), v2 = (k0 + 2 < K), v3 = (k0 + 3 < K);
    int p0 = (int)(pk & 0xFFFFu);
    int p1 = v1 ? (int)((pk >> 16) & 0xFFFFu) : 0;
    int p2 = v2 ? (int)((pk >> 32) & 0xFFFFu) : 0;
    int p3 = v3 ? (int)(pk >> 48)             : 0;

    const float4* pu = (const float4*)(g_proju + (size_t)b * NN * DD);
    const float4* pv = (const float4*)(g_projv + (size_t)b * NN * DD);

    float4 a0 = __ldg(&pu[(p0 & ~63) + lane]);
    float4 c0 = __ldg(&pv[((p0 & 63) << 6) + lane]);
    float4 a1 = __ldg(&pu[(p1 & ~63) + lane]);
    float4 c1 = __ldg(&pv[((p1 & 63) << 6) + lane]);
    float4 a2 = __ldg(&pu[(p2 & ~63) + lane]);
    float4 c2 = __ldg(&pv[((p2 & 63) << 6) + lane]);
    float4 a3 = __ldg(&pu[(p3 & ~63) + lane]);
    float4 c3 = __ldg(&pv[((p3 & 63) << 6) + lane]);

    float f1 = v1 ? 1.f : 0.f, f2 = v2 ? 1.f : 0.f, f3 = v3 ? 1.f : 0.f;

    float4 r0 = make_float4(a0.x + c0.x, a0.y + c0.y, a0.z + c0.z, a0.w + c0.w);
    float4 r1 = make_float4(f1 * (a1.x + c1.x), f1 * (a1.y + c1.y),
                            f1 * (a1.z + c1.z), f1 * (a1.w + c1.w));
    float4 r2 = make_float4(f2 * (a2.x + c2.x), f2 * (a2.y + c2.y),
                            f2 * (a2.z + c2.z), f2 * (a2.w + c2.w));
    float4 r3 = make_float4(f3 * (a3.x + c3.x), f3 * (a3.y + c3.y),
                            f3 * (a3.z + c3.z), f3 * (a3.w + c3.w));

    __stcs(&orow[lane],       r0);
    __stcs(&orow[64 + lane],  r1);
    __stcs(&orow[128 + lane], r2);
    __stcs(&orow[192 + lane], r3);
}

extern "C" void kernel_launch(void* const* d_in, const int* in_sizes, int n_in,
                              void* d_out, int out_size) {
    const int*   adj        = (const int*)d_in[0];
    const float* node_feats = (const float*)d_in[1];
    const float* eigvec     = (const float*)d_in[2];
    const float* W_lap      = (const float*)d_in[3];
    const float* W_edge     = (const float*)d_in[4];
    const float* b_edge     = (const float*)d_in[5];
    const float* type_embed = (const float*)d_in[6];
    const float* graph_tok  = (const float*)d_in[7];
    float* out = (float*)d_out;

    fused_proj_scan<<<320, 256>>>(node_feats, eigvec, W_lap, W_edge, b_edge,
                                  type_embed, graph_tok, adj, out);
    edge_kernel<<<dim3(126, 64), 256>>>(out);
}